// round 10
// baseline (speedup 1.0000x reference)
#include <cuda_runtime.h>
#include <cstdint>

// Problem constants
#define Bdim 8
#define Tdim 64
#define Ndim 128
#define Ddim 64
#define LAGn 8
#define ROWS (Bdim*Tdim*Ndim)   // 65536

typedef unsigned long long u64;

// Scratch (no cudaMalloc allowed)
// g_Q: [bt][f=64][n=128]  (TRANSPOSED)
// g_K: [bt][f=64][m=128]  (TRANSPOSED, pre-scaled by 0.125*log2(e))
// g_V: [bt][m=128][d=64]  (natural)
__device__ float g_Q[ROWS*Ddim];
__device__ float g_K[ROWS*Ddim];
__device__ float g_V[ROWS*Ddim];

// Packed fp32x2 helpers
#define PKDUP(dst, f32v) asm("mov.b64 %0, {%1, %1};" : "=l"(dst) : "f"(f32v))
#define PK2(dst, lo, hi) asm("mov.b64 %0, {%1, %2};" : "=l"(dst) : "f"(lo), "f"(hi))
#define FMA2(acc, a, b)  asm("fma.rn.f32x2 %0, %1, %2, %0;" : "+l"(acc) : "l"(a), "l"(b))
#define MUL2(acc, a)     asm("mul.rn.f32x2 %0, %0, %1;" : "+l"(acc) : "l"(a))
#define ADD2(acc, a)     asm("add.rn.f32x2 %0, %0, %1;" : "+l"(acc) : "l"(a))
#define UNPK(lo, hi, v)  asm("mov.b64 {%0, %1}, %2;" : "=f"(lo), "=f"(hi) : "l"(v))
#define EX2(y, x)        asm("ex2.approx.f32 %0, %1;" : "=f"(y) : "f"(x))

// cp.async helpers
#define CPA16(d, s)   asm volatile("cp.async.cg.shared.global [%0], [%1], 16;" :: "r"(d), "l"(s) : "memory")
#define CPA_COMMIT()  asm volatile("cp.async.commit_group;" ::: "memory")
#define CPA_WAIT0()   asm volatile("cp.async.wait_group 0;" ::: "memory")
#define CPA_WAIT1()   asm volatile("cp.async.wait_group 1;" ::: "memory")

__device__ __forceinline__ uint32_t smem_u32(const void* p) {
    uint32_t a;
    asm("{ .reg .u64 t; cvta.to.shared.u64 t, %1; cvt.u32.u64 %0, t; }" : "=r"(a) : "l"(p));
    return a;
}

// ---------------------------------------------------------------------------
// Kernel 1: QKV projection, row-pair packed. grid = (512, 3).
// ---------------------------------------------------------------------------
__global__ __launch_bounds__(256) void qkv_kernel(
    const float* __restrict__ X,
    const float* __restrict__ Wq, const float* __restrict__ bq,
    const float* __restrict__ Wk, const float* __restrict__ bk,
    const float* __restrict__ Wv, const float* __restrict__ bv)
{
    __shared__ float XsT[64*128];   // 32 KB
    __shared__ float Ws [64*64];    // 16 KB
    __shared__ float bs [64];

    const float* W; const float* bias; float scale;
    if (blockIdx.y == 0)      { W = Wq; bias = bq; scale = 1.0f; }
    else if (blockIdx.y == 1) { W = Wk; bias = bk; scale = 0.125f * 1.4426950408889634f; }
    else                      { W = Wv; bias = bv; scale = 1.0f; }

    const int bt  = blockIdx.x;
    const int r0  = bt * 128;
    const int tid = threadIdx.x;

    {
        const float4* Xg = reinterpret_cast<const float4*>(X + (size_t)r0 * 64);
        const float4* Wg = reinterpret_cast<const float4*>(W);
        #pragma unroll
        for (int q = 0; q < 4; ++q) {
            int idx4 = tid + q * 256;
            reinterpret_cast<float4*>(Ws)[idx4] = Wg[idx4];
        }
        #pragma unroll
        for (int b = 0; b < 2; ++b) {
            int blk = tid + b * 256;
            int r4  = blk >> 4;
            int f4  = blk & 15;
            float4 v0 = Xg[(r4*4+0)*16 + f4];
            float4 v1 = Xg[(r4*4+1)*16 + f4];
            float4 v2 = Xg[(r4*4+2)*16 + f4];
            float4 v3 = Xg[(r4*4+3)*16 + f4];
            int rb = (r4 ^ (f4 & 7)) << 2;
            *reinterpret_cast<float4*>(&XsT[(f4*4+0)*128 + rb]) = make_float4(v0.x, v1.x, v2.x, v3.x);
            *reinterpret_cast<float4*>(&XsT[(f4*4+1)*128 + rb]) = make_float4(v0.y, v1.y, v2.y, v3.y);
            *reinterpret_cast<float4*>(&XsT[(f4*4+2)*128 + rb]) = make_float4(v0.z, v1.z, v2.z, v3.z);
            *reinterpret_cast<float4*>(&XsT[(f4*4+3)*128 + rb]) = make_float4(v0.w, v1.w, v2.w, v3.w);
        }
        if (tid < 64) bs[tid] = bias[tid];
    }
    __syncthreads();

    const int tx = tid & 15;
    const int ty = tid >> 4;
    const int rbase = ty << 3;

    // acc[rp][d]: row-pairs (rbase+2i, rbase+2i+1) x d = tx*4+dd
    u64 acc[4][4];
    #pragma unroll
    for (int i = 0; i < 4; ++i)
        #pragma unroll
        for (int d = 0; d < 4; ++d) acc[i][d] = 0ull;

    #pragma unroll 4
    for (int k = 0; k < 64; ++k) {
        int sw = (k >> 2) & 7;
        ulonglong2 a01 = *reinterpret_cast<const ulonglong2*>(&XsT[k*128 + (((2*ty    ) ^ sw) << 2)]);
        ulonglong2 a23 = *reinterpret_cast<const ulonglong2*>(&XsT[k*128 + (((2*ty + 1) ^ sw) << 2)]);
        float4 wv = *reinterpret_cast<const float4*>(&Ws[k*64 + (tx<<2)]);
        float ws4[4] = {wv.x, wv.y, wv.z, wv.w};
        #pragma unroll
        for (int d = 0; d < 4; ++d) {
            u64 wd; PKDUP(wd, ws4[d]);
            FMA2(acc[0][d], a01.x, wd);
            FMA2(acc[1][d], a01.y, wd);
            FMA2(acc[2][d], a23.x, wd);
            FMA2(acc[3][d], a23.y, wd);
        }
    }

    float o[8][4];
    #pragma unroll
    for (int i = 0; i < 4; ++i)
        #pragma unroll
        for (int d = 0; d < 4; ++d)
            UNPK(o[2*i][d], o[2*i+1][d], acc[i][d]);
    #pragma unroll
    for (int i = 0; i < 8; ++i)
        #pragma unroll
        for (int j = 0; j < 4; ++j)
            o[i][j] = fmaxf(o[i][j] + bs[(tx<<2)+j], 0.0f) * scale;

    if (blockIdx.y == 2) {
        #pragma unroll
        for (int i = 0; i < 8; ++i) {
            int r = r0 + rbase + i;
            *reinterpret_cast<float4*>(&g_V[(size_t)r*64 + (tx<<2)]) =
                make_float4(o[i][0], o[i][1], o[i][2], o[i][3]);
        }
    } else {
        float* outp = blockIdx.y ? g_K : g_Q;
        #pragma unroll
        for (int j = 0; j < 4; ++j) {
            int d = (tx<<2) + j;
            float* base = &outp[(size_t)bt*8192 + d*128 + rbase];
            *reinterpret_cast<float4*>(base)     = make_float4(o[0][j], o[1][j], o[2][j], o[3][j]);
            *reinterpret_cast<float4*>(base + 4) = make_float4(o[4][j], o[5][j], o[6][j], o[7][j]);
        }
    }
}

// ---------------------------------------------------------------------------
// Kernel 2: fused lag-attention + output projection.
// grid = B*T*2, 128 threads, 48 KB smem -> 4 CTAs/SM (launch_bounds(128,4)).
// 32-key chunks (4 per lag). Row-pair packed FFMA2.
// P layout: [32 m][32 rp u64]; writer key tx&7 (m = 2*tx+mm), reader (m>>1)&7.
// aggT layout: [64 c][32 rp u64] with rp ^ ((c>>2 &7)<<1).
// 3 barriers per chunk via group accounting (see loop comments).
// ---------------------------------------------------------------------------
#define SM_Q 0
#define SM_K 4096
#define SM_V 6144
#define SM_P 8192
#define SMEM_ATTN (12288*4)   // 48 KB

__global__ __launch_bounds__(128, 4) void attn_kernel(
    const float* __restrict__ Wo, const float* __restrict__ bo,
    float* __restrict__ out)
{
    extern __shared__ float sm[];
    float* Qst = sm + SM_Q;     // [64 f][64 r]           16 KB
    float* KsT = sm + SM_K;     // [64 f][32 m]            8 KB
    float* Vs  = sm + SM_V;     // [32 m][64 d]            8 KB
    float* Pp  = sm + SM_P;     // [32 m][32 rp u64]       8 KB (region is 16 KB)
    float* aggT = sm + SM_P;    // alias: [64 c][32 rp u64] 16 KB
    float* Wos  = sm + SM_K;    // alias: [64 c][64 d]     16 KB (K+V regions)

    const int gid  = blockIdx.x;
    const int half = gid & 1;
    const int bt   = gid >> 1;
    const int t    = bt & (Tdim - 1);
    const int tid  = threadIdx.x;
    const int tx   = tid & 15;
    const int ty   = tid >> 4;          // 0..7
    const int rbase = ty << 3;

    const uint32_t sQ = smem_u32(Qst);
    const uint32_t sK = smem_u32(KsT);
    const uint32_t sV = smem_u32(Vs);

    // Prologue: Q tile + first K/V chunk via cp.async (one group).
    {
        const float4* Qg = reinterpret_cast<const float4*>(g_Q + (size_t)bt*8192) + half*16;
        const float*  Kg = g_K + (size_t)bt*8192;
        const float*  Vg = g_V + (size_t)bt*8192;
        #pragma unroll
        for (int q = 0; q < 8; ++q) {
            int idx4 = tid + q * 128;        // 0..1023
            CPA16(sQ + (uint32_t)idx4*16, Qg + (idx4 >> 4)*32 + (idx4 & 15));
        }
        #pragma unroll
        for (int q = 0; q < 4; ++q) {
            int idx4 = tid + q * 128;        // 0..511
            int f = idx4 >> 3, u = idx4 & 7;
            CPA16(sK + (uint32_t)idx4*16, Kg + f*128 + u*4);
            CPA16(sV + (uint32_t)idx4*16, Vg + idx4*4);
        }
        CPA_COMMIT();
    }

    u64 dpack[4];   // packed denominators, pairs (rbase+2i, rbase+2i+1)
    u64 Op[4][4];   // [rp][d]
    #pragma unroll
    for (int i = 0; i < 4; ++i) {
        dpack[i] = 0ull;
        #pragma unroll
        for (int d = 0; d < 4; ++d) Op[i][d] = 0ull;
    }

    const int nvalid  = (t + 1 < LAGn) ? (t + 1) : LAGn;
    const int nchunks = nvalid * 4;

    // Hoisted P-store offsets (floats) for this thread's 4 row-pairs.
    int poff[4];
    #pragma unroll
    for (int i = 0; i < 4; ++i) {
        int rp = (ty<<2) + i;
        poff[i] = (((rp>>1) ^ (tx&7)) << 2) + ((rp & 1) << 1);
    }

    for (int ic = 0; ic < nchunks; ++ic) {
        // Pending groups here (ic>0): {K(ic), V(ic)} -> wait1 releases K(ic).
        if (ic == 0) { CPA_WAIT0(); } else { CPA_WAIT1(); }
        __syncthreads();   // K(ic) visible; Pp free (prev GEMM2 done at its last barrier)

        // ---- GEMM1: S = Q·K^T, sa[rp 0..3][m 0..1], m = 2*tx+mm ----
        u64 sa[4][2];
        #pragma unroll
        for (int i = 0; i < 4; ++i) { sa[i][0] = 0ull; sa[i][1] = 0ull; }

        #pragma unroll 8
        for (int k = 0; k < 64; ++k) {
            ulonglong2 a01 = *reinterpret_cast<const ulonglong2*>(&Qst[k*64 + rbase]);
            ulonglong2 a23 = *reinterpret_cast<const ulonglong2*>(&Qst[k*64 + rbase + 4]);
            float2 bv = *reinterpret_cast<const float2*>(&KsT[k*32 + (tx<<1)]);
            u64 b0; PKDUP(b0, bv.x);
            u64 b1; PKDUP(b1, bv.y);
            FMA2(sa[0][0], a01.x, b0);
            FMA2(sa[1][0], a01.y, b0);
            FMA2(sa[2][0], a23.x, b0);
            FMA2(sa[3][0], a23.y, b0);
            FMA2(sa[0][1], a01.x, b1);
            FMA2(sa[1][1], a01.y, b1);
            FMA2(sa[2][1], a23.x, b1);
            FMA2(sa[3][1], a23.y, b1);
        }

        // ---- 2^s + packed denom + P store ----
        #pragma unroll
        for (int i = 0; i < 4; ++i) {
            #pragma unroll
            for (int mm = 0; mm < 2; ++mm) {
                float lo, hi;
                UNPK(lo, hi, sa[i][mm]);
                float elo, ehi;
                EX2(elo, lo); EX2(ehi, hi);
                u64 pe; PK2(pe, elo, ehi);
                ADD2(dpack[i], pe);
                *reinterpret_cast<u64*>(&Pp[((tx<<1)+mm)*64 + poff[i]]) = pe;
            }
        }

        // V(ic) is the only pending group -> wait0 drains it.
        CPA_WAIT0();
        __syncthreads();   // P visible, V visible, KsT free

        // Prefetch K(ic+1) (overlaps GEMM2).
        if (ic + 1 < nchunks) {
            const float* Kg = g_K + (size_t)(bt - ((ic+1)>>2)) * 8192 + (((ic+1)&3) << 5);
            #pragma unroll
            for (int q = 0; q < 4; ++q) {
                int idx4 = tid + q * 128;
                int f = idx4 >> 3, u = idx4 & 7;
                CPA16(sK + (uint32_t)idx4*16, Kg + f*128 + u*4);
            }
        }
        CPA_COMMIT();

        // ---- GEMM2: O += P @ V ----
        #pragma unroll 4
        for (int m = 0; m < 32; ++m) {
            const int x = (m >> 1) & 7;
            ulonglong2 p01 = *reinterpret_cast<const ulonglong2*>(
                &Pp[m*64 + ((((ty<<1)    ) ^ x) << 2)]);
            ulonglong2 p23 = *reinterpret_cast<const ulonglong2*>(
                &Pp[m*64 + ((((ty<<1) | 1) ^ x) << 2)]);
            float4 vv = *reinterpret_cast<const float4*>(&Vs[m*64 + (tx<<2)]);
            float vs4[4] = {vv.x, vv.y, vv.z, vv.w};
            #pragma unroll
            for (int d = 0; d < 4; ++d) {
                u64 vd; PKDUP(vd, vs4[d]);
                FMA2(Op[0][d], p01.x, vd);
                FMA2(Op[1][d], p01.y, vd);
                FMA2(Op[2][d], p23.x, vd);
                FMA2(Op[3][d], p23.y, vd);
            }
        }
        __syncthreads();   // Vs free

        // Prefetch V(ic+1) (overlaps next GEMM1).
        if (ic + 1 < nchunks) {
            const float* Vg = g_V + ((size_t)(bt - ((ic+1)>>2)) * 128 + (((ic+1)&3) << 5)) * 64;
            #pragma unroll
            for (int q = 0; q < 4; ++q) {
                int idx4 = tid + q * 128;
                CPA16(sV + (uint32_t)idx4*16, Vg + idx4*4);
            }
        }
        CPA_COMMIT();
    }

    // ---- denominators: reduce over 16 tx lanes, packed inverses ----
    const float padadd = (float)(LAGn - nvalid) * 128.0f;   // 2^0 per padded key
    u64 invp[4];
    #pragma unroll
    for (int i = 0; i < 4; ++i) {
        float d0, d1;
        UNPK(d0, d1, dpack[i]);
        d0 += __shfl_xor_sync(0xffffffffu, d0, 1);
        d1 += __shfl_xor_sync(0xffffffffu, d1, 1);
        d0 += __shfl_xor_sync(0xffffffffu, d0, 2);
        d1 += __shfl_xor_sync(0xffffffffu, d1, 2);
        d0 += __shfl_xor_sync(0xffffffffu, d0, 4);
        d1 += __shfl_xor_sync(0xffffffffu, d1, 4);
        d0 += __shfl_xor_sync(0xffffffffu, d0, 8);
        d1 += __shfl_xor_sync(0xffffffffu, d1, 8);
        PK2(invp[i], 1.0f / (d0 + padadd), 1.0f / (d1 + padadd));
    }

    CPA_WAIT0();
    __syncthreads();   // drain; all smem reusable

    // agg (normalized, row-pair u64) -> aggT; Wo[0:64] -> Wos.
    {
        const int key2 = (tx & 7) << 1;
        #pragma unroll
        for (int i = 0; i < 4; ++i) {
            const int rp = (ty<<2) + i;
            #pragma unroll
            for (int dd = 0; dd < 4; ++dd) {
                MUL2(Op[i][dd], invp[i]);
                const int c = (tx<<2) + dd;
                *reinterpret_cast<u64*>(&aggT[c*64 + ((rp ^ key2) << 1)]) = Op[i][dd];
            }
        }
        const float4* Wg = reinterpret_cast<const float4*>(Wo);
        #pragma unroll
        for (int q = 0; q < 8; ++q) {
            int idx4 = tid + q * 128;   // 0..1023 -> Wo rows 0..63
            reinterpret_cast<float4*>(Wos)[idx4] = Wg[idx4];
        }
    }
    __syncthreads();

    // ---- epilogue pass 1: ec = Q @ Wo[0:64] ----
    u64 ec[4][4];
    #pragma unroll
    for (int i = 0; i < 4; ++i)
        #pragma unroll
        for (int d = 0; d < 4; ++d) ec[i][d] = 0ull;

    #pragma unroll 4
    for (int c = 0; c < 64; ++c) {
        ulonglong2 a01 = *reinterpret_cast<const ulonglong2*>(&Qst[c*64 + rbase]);
        ulonglong2 a23 = *reinterpret_cast<const ulonglong2*>(&Qst[c*64 + rbase + 4]);
        float4 wv = *reinterpret_cast<const float4*>(&Wos[c*64 + (tx<<2)]);
        float ws4[4] = {wv.x, wv.y, wv.z, wv.w};
        #pragma unroll
        for (int d = 0; d < 4; ++d) {
            u64 wd; PKDUP(wd, ws4[d]);
            FMA2(ec[0][d], a01.x, wd);
            FMA2(ec[1][d], a01.y, wd);
            FMA2(ec[2][d], a23.x, wd);
            FMA2(ec[3][d], a23.y, wd);
        }
    }
    __syncthreads();   // Wos reads done

    // Load Wo[64:128]
    {
        const float4* Wg = reinterpret_cast<const float4*>(Wo) + 1024;
        #pragma unroll
        for (int q = 0; q < 8; ++q) {
            int idx4 = tid + q * 128;
            reinterpret_cast<float4*>(Wos)[idx4] = Wg[idx4];
        }
    }
    __syncthreads();

    // ---- epilogue pass 2: ec += agg @ Wo[64:128] ----
    #pragma unroll 4
    for (int c = 0; c < 64; ++c) {
        const int y = ((c >> 2) & 7) << 1;
        ulonglong2 a01 = *reinterpret_cast<const ulonglong2*>(
            &aggT[c*64 + ((((ty<<2)    ) ^ y) << 1)]);
        ulonglong2 a23 = *reinterpret_cast<const ulonglong2*>(
            &aggT[c*64 + ((((ty<<2) + 2) ^ y) << 1)]);
        float4 wv = *reinterpret_cast<const float4*>(&Wos[c*64 + (tx<<2)]);
        float ws4[4] = {wv.x, wv.y, wv.z, wv.w};
        #pragma unroll
        for (int d = 0; d < 4; ++d) {
            u64 wd; PKDUP(wd, ws4[d]);
            FMA2(ec[0][d], a01.x, wd);
            FMA2(ec[1][d], a01.y, wd);
            FMA2(ec[2][d], a23.x, wd);
            FMA2(ec[3][d], a23.y, wd);
        }
    }

    float bo4[4];
    #pragma unroll
    for (int j = 0; j < 4; ++j) bo4[j] = bo[(tx<<2) + j];

    #pragma unroll
    for (int i = 0; i < 4; ++i) {
        float e0[4], e1[4];
        #pragma unroll
        for (int d = 0; d < 4; ++d) UNPK(e0[d], e1[d], ec[i][d]);
        size_t row0 = (size_t)bt * Ndim + half*64 + rbase + 2*i;
        float4 o0, o1;
        o0.x = fmaxf(e0[0] + bo4[0], 0.0f);
        o0.y = fmaxf(e0[1] + bo4[1], 0.0f);
        o0.z = fmaxf(e0[2] + bo4[2], 0.0f);
        o0.w = fmaxf(e0[3] + bo4[3], 0.0f);
        o1.x = fmaxf(e1[0] + bo4[0], 0.0f);
        o1.y = fmaxf(e1[1] + bo4[1], 0.0f);
        o1.z = fmaxf(e1[2] + bo4[2], 0.0f);
        o1.w = fmaxf(e1[3] + bo4[3], 0.0f);
        *reinterpret_cast<float4*>(&out[row0 * Ddim + (tx<<2)])       = o0;
        *reinterpret_cast<float4*>(&out[(row0 + 1) * Ddim + (tx<<2)]) = o1;
    }
}

// ---------------------------------------------------------------------------
extern "C" void kernel_launch(void* const* d_in, const int* in_sizes, int n_in,
                              void* d_out, int out_size)
{
    const float* X  = (const float*)d_in[0];
    const float* Wq = (const float*)d_in[1];
    const float* bq = (const float*)d_in[2];
    const float* Wk = (const float*)d_in[3];
    const float* bk = (const float*)d_in[4];
    const float* Wv = (const float*)d_in[5];
    const float* bv = (const float*)d_in[6];
    const float* Wo = (const float*)d_in[7];
    const float* bo = (const float*)d_in[8];
    float* out = (float*)d_out;

    cudaFuncSetAttribute(attn_kernel,
                         cudaFuncAttributeMaxDynamicSharedMemorySize, SMEM_ATTN);

    qkv_kernel<<<dim3(Bdim*Tdim, 3, 1), 256>>>(X, Wq, bq, Wk, bk, Wv, bv);
    attn_kernel<<<Bdim*Tdim*2, 128, SMEM_ATTN>>>(Wo, bo, out);
}

// round 11
// speedup vs baseline: 1.0761x; 1.0761x over previous
#include <cuda_runtime.h>
#include <cstdint>

// Problem constants
#define Bdim 8
#define Tdim 64
#define Ndim 128
#define Ddim 64
#define LAGn 8
#define ROWS (Bdim*Tdim*Ndim)   // 65536

typedef unsigned long long u64;

// Scratch (no cudaMalloc allowed)
// g_Q: [bt][f=64][n=128]  (TRANSPOSED)
// g_K: [bt][f=64][m=128]  (TRANSPOSED, pre-scaled by 0.125*log2(e))
// g_V: [bt][m=128][d=64]  (natural)
__device__ float g_Q[ROWS*Ddim];
__device__ float g_K[ROWS*Ddim];
__device__ float g_V[ROWS*Ddim];

// Packed fp32x2 helpers
#define PKDUP(dst, f32v) asm("mov.b64 %0, {%1, %1};" : "=l"(dst) : "f"(f32v))
#define PK2(dst, lo, hi) asm("mov.b64 %0, {%1, %2};" : "=l"(dst) : "f"(lo), "f"(hi))
#define FMA2(acc, a, b)  asm("fma.rn.f32x2 %0, %1, %2, %0;" : "+l"(acc) : "l"(a), "l"(b))
#define MUL2(acc, a)     asm("mul.rn.f32x2 %0, %0, %1;" : "+l"(acc) : "l"(a))
#define ADD2(acc, a)     asm("add.rn.f32x2 %0, %0, %1;" : "+l"(acc) : "l"(a))
#define UNPK(lo, hi, v)  asm("mov.b64 {%0, %1}, %2;" : "=f"(lo), "=f"(hi) : "l"(v))
#define EX2(y, x)        asm("ex2.approx.f32 %0, %1;" : "=f"(y) : "f"(x))

// cp.async helpers
#define CPA16(d, s)   asm volatile("cp.async.cg.shared.global [%0], [%1], 16;" :: "r"(d), "l"(s) : "memory")
#define CPA_COMMIT()  asm volatile("cp.async.commit_group;" ::: "memory")
#define CPA_WAIT0()   asm volatile("cp.async.wait_group 0;" ::: "memory")
#define CPA_WAIT1()   asm volatile("cp.async.wait_group 1;" ::: "memory")

__device__ __forceinline__ uint32_t smem_u32(const void* p) {
    uint32_t a;
    asm("{ .reg .u64 t; cvta.to.shared.u64 t, %1; cvt.u32.u64 %0, t; }" : "=r"(a) : "l"(p));
    return a;
}

// ---------------------------------------------------------------------------
// Kernel 1: QKV projection, row-pair packed (R10 version). grid = (512, 3).
// ---------------------------------------------------------------------------
__global__ __launch_bounds__(256) void qkv_kernel(
    const float* __restrict__ X,
    const float* __restrict__ Wq, const float* __restrict__ bq,
    const float* __restrict__ Wk, const float* __restrict__ bk,
    const float* __restrict__ Wv, const float* __restrict__ bv)
{
    __shared__ float XsT[64*128];   // 32 KB
    __shared__ float Ws [64*64];    // 16 KB
    __shared__ float bs [64];

    const float* W; const float* bias; float scale;
    if (blockIdx.y == 0)      { W = Wq; bias = bq; scale = 1.0f; }
    else if (blockIdx.y == 1) { W = Wk; bias = bk; scale = 0.125f * 1.4426950408889634f; }
    else                      { W = Wv; bias = bv; scale = 1.0f; }

    const int bt  = blockIdx.x;
    const int r0  = bt * 128;
    const int tid = threadIdx.x;

    {
        const float4* Xg = reinterpret_cast<const float4*>(X + (size_t)r0 * 64);
        const float4* Wg = reinterpret_cast<const float4*>(W);
        #pragma unroll
        for (int q = 0; q < 4; ++q) {
            int idx4 = tid + q * 256;
            reinterpret_cast<float4*>(Ws)[idx4] = Wg[idx4];
        }
        #pragma unroll
        for (int b = 0; b < 2; ++b) {
            int blk = tid + b * 256;
            int r4  = blk >> 4;
            int f4  = blk & 15;
            float4 v0 = Xg[(r4*4+0)*16 + f4];
            float4 v1 = Xg[(r4*4+1)*16 + f4];
            float4 v2 = Xg[(r4*4+2)*16 + f4];
            float4 v3 = Xg[(r4*4+3)*16 + f4];
            int rb = (r4 ^ (f4 & 7)) << 2;
            *reinterpret_cast<float4*>(&XsT[(f4*4+0)*128 + rb]) = make_float4(v0.x, v1.x, v2.x, v3.x);
            *reinterpret_cast<float4*>(&XsT[(f4*4+1)*128 + rb]) = make_float4(v0.y, v1.y, v2.y, v3.y);
            *reinterpret_cast<float4*>(&XsT[(f4*4+2)*128 + rb]) = make_float4(v0.z, v1.z, v2.z, v3.z);
            *reinterpret_cast<float4*>(&XsT[(f4*4+3)*128 + rb]) = make_float4(v0.w, v1.w, v2.w, v3.w);
        }
        if (tid < 64) bs[tid] = bias[tid];
    }
    __syncthreads();

    const int tx = tid & 15;
    const int ty = tid >> 4;
    const int rbase = ty << 3;

    u64 acc[4][4];
    #pragma unroll
    for (int i = 0; i < 4; ++i)
        #pragma unroll
        for (int d = 0; d < 4; ++d) acc[i][d] = 0ull;

    #pragma unroll 4
    for (int k = 0; k < 64; ++k) {
        int sw = (k >> 2) & 7;
        ulonglong2 a01 = *reinterpret_cast<const ulonglong2*>(&XsT[k*128 + (((2*ty    ) ^ sw) << 2)]);
        ulonglong2 a23 = *reinterpret_cast<const ulonglong2*>(&XsT[k*128 + (((2*ty + 1) ^ sw) << 2)]);
        float4 wv = *reinterpret_cast<const float4*>(&Ws[k*64 + (tx<<2)]);
        float ws4[4] = {wv.x, wv.y, wv.z, wv.w};
        #pragma unroll
        for (int d = 0; d < 4; ++d) {
            u64 wd; PKDUP(wd, ws4[d]);
            FMA2(acc[0][d], a01.x, wd);
            FMA2(acc[1][d], a01.y, wd);
            FMA2(acc[2][d], a23.x, wd);
            FMA2(acc[3][d], a23.y, wd);
        }
    }

    float o[8][4];
    #pragma unroll
    for (int i = 0; i < 4; ++i)
        #pragma unroll
        for (int d = 0; d < 4; ++d)
            UNPK(o[2*i][d], o[2*i+1][d], acc[i][d]);
    #pragma unroll
    for (int i = 0; i < 8; ++i)
        #pragma unroll
        for (int j = 0; j < 4; ++j)
            o[i][j] = fmaxf(o[i][j] + bs[(tx<<2)+j], 0.0f) * scale;

    if (blockIdx.y == 2) {
        #pragma unroll
        for (int i = 0; i < 8; ++i) {
            int r = r0 + rbase + i;
            *reinterpret_cast<float4*>(&g_V[(size_t)r*64 + (tx<<2)]) =
                make_float4(o[i][0], o[i][1], o[i][2], o[i][3]);
        }
    } else {
        float* outp = blockIdx.y ? g_K : g_Q;
        #pragma unroll
        for (int j = 0; j < 4; ++j) {
            int d = (tx<<2) + j;
            float* base = &outp[(size_t)bt*8192 + d*128 + rbase];
            *reinterpret_cast<float4*>(base)     = make_float4(o[0][j], o[1][j], o[2][j], o[3][j]);
            *reinterpret_cast<float4*>(base + 4) = make_float4(o[4][j], o[5][j], o[6][j], o[7][j]);
        }
    }
}

// ---------------------------------------------------------------------------
// Kernel 2: fused lag-attention + output projection.
// grid = 512 (one per (b,t)), 256 threads, 96 KB smem -> 2 CTAs/SM (16 warps).
// 64-key chunks (2 per lag); R9's per-thread tile (8 rows x 4 m / 4 d).
// P layout: [64 m][32 units x 16B], unit U = (rp>>1) ^ key, key = (m>>2)&15;
//   each unit holds row-pairs (2U',2U'+1) as two u64 halves (half = rp&1).
// aggT layout: [64 c][32 units x 16B], key = (c>>2)&15, same unit scheme.
// 3 barriers per chunk via cp.async group accounting.
// ---------------------------------------------------------------------------
#define SM_Q 0
#define SM_K 8192
#define SM_V 12288
#define SM_P 16384
#define SMEM_ATTN (24576*4)   // 96 KB

__global__ __launch_bounds__(256, 2) void attn_kernel(
    const float* __restrict__ Wo, const float* __restrict__ bo,
    float* __restrict__ out)
{
    extern __shared__ float sm[];
    float* Qst = sm + SM_Q;     // [64 f][128 r]          32 KB
    float* KsT = sm + SM_K;     // [64 f][64 m]           16 KB
    float* Vs  = sm + SM_V;     // [64 m][64 d]           16 KB
    float* Pp  = sm + SM_P;     // [64 m][128 f swizzled] 32 KB
    float* aggT = sm + SM_P;    // alias: [64 c][128 f swizzled]
    float* Wos  = sm + SM_K;    // alias: [128 c][64 d]   32 KB (K+V regions)

    const int bt   = blockIdx.x;
    const int t    = bt & (Tdim - 1);
    const int tid  = threadIdx.x;
    const int tx   = tid & 15;
    const int ty   = tid >> 4;          // 0..15
    const int rbase = ty << 3;          // rows rbase..rbase+7

    const uint32_t sK = smem_u32(KsT);
    const uint32_t sV = smem_u32(Vs);

    // Prologue: Q tile (linear 32KB) + first K/V chunk via cp.async (one group).
    {
        const float4* Qg = reinterpret_cast<const float4*>(g_Q + (size_t)bt*8192);
        const float*  Kg = g_K + (size_t)bt*8192;
        const float*  Vg = g_V + (size_t)bt*8192;
        const uint32_t sQ = smem_u32(Qst);
        #pragma unroll
        for (int q = 0; q < 8; ++q) {
            int idx4 = tid + q * 256;        // 0..2047
            CPA16(sQ + (uint32_t)idx4*16, Qg + idx4);
        }
        #pragma unroll
        for (int q = 0; q < 4; ++q) {
            int idx4 = tid + q * 256;        // 0..1023
            int f = idx4 >> 4, u = idx4 & 15;
            CPA16(sK + (uint32_t)idx4*16, Kg + f*128 + u*4);
            CPA16(sV + (uint32_t)idx4*16, Vg + idx4*4);
        }
        CPA_COMMIT();
    }

    u64 dpack[4];   // packed denominators, row pairs rp = ty*4+i
    u64 Op[4][4];   // [rp][d]
    #pragma unroll
    for (int i = 0; i < 4; ++i) {
        dpack[i] = 0ull;
        #pragma unroll
        for (int d = 0; d < 4; ++d) Op[i][d] = 0ull;
    }

    const int nvalid  = (t + 1 < LAGn) ? (t + 1) : LAGn;
    const int nchunks = nvalid * 2;

    // Hoisted P-store float offsets within an m-row (128 floats):
    // U = (rp>>1) ^ tx (writer key tx == (m>>2)&15 since m = 4*tx+mm)
    int poff[4];
    #pragma unroll
    for (int i = 0; i < 4; ++i) {
        int rp = (ty<<2) + i;
        poff[i] = ((((rp>>1) ^ tx) & 31) << 2) + ((rp & 1) << 1);
    }

    for (int ic = 0; ic < nchunks; ++ic) {
        // Pending here (ic>0): {K(ic), V(ic)} -> wait1 releases K(ic).
        if (ic == 0) { CPA_WAIT0(); } else { CPA_WAIT1(); }
        __syncthreads();   // K(ic) visible; Pp free (prev GEMM2 done)

        // ---- GEMM1: S = Q·K^T, sa[rp 0..3][m 0..3], m = 4*tx+mm ----
        u64 sa[4][4];
        #pragma unroll
        for (int i = 0; i < 4; ++i)
            #pragma unroll
            for (int m = 0; m < 4; ++m) sa[i][m] = 0ull;

        #pragma unroll 4
        for (int k = 0; k < 64; ++k) {
            ulonglong2 a01 = *reinterpret_cast<const ulonglong2*>(&Qst[k*128 + rbase]);
            ulonglong2 a23 = *reinterpret_cast<const ulonglong2*>(&Qst[k*128 + rbase + 4]);
            float4 bv = *reinterpret_cast<const float4*>(&KsT[k*64 + (tx<<2)]);
            float bs4[4] = {bv.x, bv.y, bv.z, bv.w};
            #pragma unroll
            for (int m = 0; m < 4; ++m) {
                u64 bd; PKDUP(bd, bs4[m]);
                FMA2(sa[0][m], a01.x, bd);
                FMA2(sa[1][m], a01.y, bd);
                FMA2(sa[2][m], a23.x, bd);
                FMA2(sa[3][m], a23.y, bd);
            }
        }

        // ---- 2^s + packed denom + P store ----
        #pragma unroll
        for (int i = 0; i < 4; ++i) {
            #pragma unroll
            for (int mm = 0; mm < 4; ++mm) {
                float lo, hi;
                UNPK(lo, hi, sa[i][mm]);
                float elo, ehi;
                EX2(elo, lo); EX2(ehi, hi);
                u64 pe; PK2(pe, elo, ehi);
                ADD2(dpack[i], pe);
                *reinterpret_cast<u64*>(&Pp[((tx<<2)+mm)*128 + poff[i]]) = pe;
            }
        }

        // V(ic) is the only pending group -> wait0 drains it.
        CPA_WAIT0();
        __syncthreads();   // P visible, V visible, KsT free

        // Prefetch K(ic+1) into the freed K buffer (overlaps GEMM2).
        if (ic + 1 < nchunks) {
            const float* Kg = g_K + (size_t)(bt - ((ic+1)>>1)) * 8192 + (((ic+1)&1) << 6);
            #pragma unroll
            for (int q = 0; q < 4; ++q) {
                int idx4 = tid + q * 256;
                int f = idx4 >> 4, u = idx4 & 15;
                CPA16(sK + (uint32_t)idx4*16, Kg + f*128 + u*4);
            }
            CPA_COMMIT();
        }

        // ---- GEMM2: O += P @ V; key x = (m>>2)&15 hoisted per 4-m block ----
        #pragma unroll 4
        for (int x = 0; x < 16; ++x) {
            const int off01 = ((((ty<<1)    ) ^ x) & 31) << 2;
            const int off23 = ((((ty<<1) | 1) ^ x) & 31) << 2;
            #pragma unroll
            for (int mm = 0; mm < 4; ++mm) {
                const int m = (x<<2) + mm;
                ulonglong2 p01 = *reinterpret_cast<const ulonglong2*>(&Pp[m*128 + off01]);
                ulonglong2 p23 = *reinterpret_cast<const ulonglong2*>(&Pp[m*128 + off23]);
                float4 vv = *reinterpret_cast<const float4*>(&Vs[m*64 + (tx<<2)]);
                float vs4[4] = {vv.x, vv.y, vv.z, vv.w};
                #pragma unroll
                for (int d = 0; d < 4; ++d) {
                    u64 vd; PKDUP(vd, vs4[d]);
                    FMA2(Op[0][d], p01.x, vd);
                    FMA2(Op[1][d], p01.y, vd);
                    FMA2(Op[2][d], p23.x, vd);
                    FMA2(Op[3][d], p23.y, vd);
                }
            }
        }
        __syncthreads();   // Vs free

        // Prefetch V(ic+1) (overlaps next GEMM1).
        if (ic + 1 < nchunks) {
            const float* Vg = g_V + ((size_t)(bt - ((ic+1)>>1)) * 128 + (((ic+1)&1) << 6)) * 64;
            #pragma unroll
            for (int q = 0; q < 4; ++q) {
                int idx4 = tid + q * 256;
                CPA16(sV + (uint32_t)idx4*16, Vg + idx4*4);
            }
            CPA_COMMIT();
        }
    }

    // ---- denominators: reduce over 16 tx lanes, packed inverses ----
    const float padadd = (float)(LAGn - nvalid) * 128.0f;   // 2^0 per padded key
    u64 invp[4];
    #pragma unroll
    for (int i = 0; i < 4; ++i) {
        float d0, d1;
        UNPK(d0, d1, dpack[i]);
        d0 += __shfl_xor_sync(0xffffffffu, d0, 1);
        d1 += __shfl_xor_sync(0xffffffffu, d1, 1);
        d0 += __shfl_xor_sync(0xffffffffu, d0, 2);
        d1 += __shfl_xor_sync(0xffffffffu, d1, 2);
        d0 += __shfl_xor_sync(0xffffffffu, d0, 4);
        d1 += __shfl_xor_sync(0xffffffffu, d1, 4);
        d0 += __shfl_xor_sync(0xffffffffu, d0, 8);
        d1 += __shfl_xor_sync(0xffffffffu, d1, 8);
        PK2(invp[i], 1.0f / (d0 + padadd), 1.0f / (d1 + padadd));
    }

    CPA_WAIT0();
    __syncthreads();   // drain; all smem reusable

    // agg (normalized, row-pair u64) -> aggT (key = (c>>2)&15 = tx); Wo -> Wos (32KB).
    #pragma unroll
    for (int i = 0; i < 4; ++i) {
        const int rp = (ty<<2) + i;
        const int foff = ((((rp>>1) ^ tx) & 31) << 2) + ((rp & 1) << 1);
        #pragma unroll
        for (int dd = 0; dd < 4; ++dd) {
            MUL2(Op[i][dd], invp[i]);
            *reinterpret_cast<u64*>(&aggT[((tx<<2)+dd)*128 + foff]) = Op[i][dd];
        }
    }
    {
        const float4* Wg = reinterpret_cast<const float4*>(Wo);
        #pragma unroll
        for (int q = 0; q < 8; ++q) {
            int idx4 = tid + q * 256;   // 0..2047 (full 128x64)
            reinterpret_cast<float4*>(Wos)[idx4] = Wg[idx4];
        }
    }
    __syncthreads();

    // ---- epilogue: out = relu([Q | agg] @ Wo + bo), single pass ----
    u64 ec[4][4];
    #pragma unroll
    for (int i = 0; i < 4; ++i)
        #pragma unroll
        for (int d = 0; d < 4; ++d) ec[i][d] = 0ull;

    #pragma unroll 4
    for (int c = 0; c < 64; ++c) {
        ulonglong2 a01 = *reinterpret_cast<const ulonglong2*>(&Qst[c*128 + rbase]);
        ulonglong2 a23 = *reinterpret_cast<const ulonglong2*>(&Qst[c*128 + rbase + 4]);
        float4 wv = *reinterpret_cast<const float4*>(&Wos[c*64 + (tx<<2)]);
        float ws4[4] = {wv.x, wv.y, wv.z, wv.w};
        #pragma unroll
        for (int d = 0; d < 4; ++d) {
            u64 wd; PKDUP(wd, ws4[d]);
            FMA2(ec[0][d], a01.x, wd);
            FMA2(ec[1][d], a01.y, wd);
            FMA2(ec[2][d], a23.x, wd);
            FMA2(ec[3][d], a23.y, wd);
        }
    }
    #pragma unroll 4
    for (int x = 0; x < 16; ++x) {
        const int off01 = ((((ty<<1)    ) ^ x) & 31) << 2;
        const int off23 = ((((ty<<1) | 1) ^ x) & 31) << 2;
        #pragma unroll
        for (int cc = 0; cc < 4; ++cc) {
            const int c = (x<<2) + cc;
            ulonglong2 a01 = *reinterpret_cast<const ulonglong2*>(&aggT[c*128 + off01]);
            ulonglong2 a23 = *reinterpret_cast<const ulonglong2*>(&aggT[c*128 + off23]);
            float4 wv = *reinterpret_cast<const float4*>(&Wos[(64+c)*64 + (tx<<2)]);
            float ws4[4] = {wv.x, wv.y, wv.z, wv.w};
            #pragma unroll
            for (int d = 0; d < 4; ++d) {
                u64 wd; PKDUP(wd, ws4[d]);
                FMA2(ec[0][d], a01.x, wd);
                FMA2(ec[1][d], a01.y, wd);
                FMA2(ec[2][d], a23.x, wd);
                FMA2(ec[3][d], a23.y, wd);
            }
        }
    }

    float bo4[4];
    #pragma unroll
    for (int j = 0; j < 4; ++j) bo4[j] = bo[(tx<<2) + j];

    #pragma unroll
    for (int i = 0; i < 4; ++i) {
        float e0[4], e1[4];
        #pragma unroll
        for (int d = 0; d < 4; ++d) UNPK(e0[d], e1[d], ec[i][d]);
        size_t row0 = (size_t)bt * Ndim + rbase + 2*i;
        float4 o0, o1;
        o0.x = fmaxf(e0[0] + bo4[0], 0.0f);
        o0.y = fmaxf(e0[1] + bo4[1], 0.0f);
        o0.z = fmaxf(e0[2] + bo4[2], 0.0f);
        o0.w = fmaxf(e0[3] + bo4[3], 0.0f);
        o1.x = fmaxf(e1[0] + bo4[0], 0.0f);
        o1.y = fmaxf(e1[1] + bo4[1], 0.0f);
        o1.z = fmaxf(e1[2] + bo4[2], 0.0f);
        o1.w = fmaxf(e1[3] + bo4[3], 0.0f);
        *reinterpret_cast<float4*>(&out[row0 * Ddim + (tx<<2)])       = o0;
        *reinterpret_cast<float4*>(&out[(row0 + 1) * Ddim + (tx<<2)]) = o1;
    }
}

// ---------------------------------------------------------------------------
extern "C" void kernel_launch(void* const* d_in, const int* in_sizes, int n_in,
                              void* d_out, int out_size)
{
    const float* X  = (const float*)d_in[0];
    const float* Wq = (const float*)d_in[1];
    const float* bq = (const float*)d_in[2];
    const float* Wk = (const float*)d_in[3];
    const float* bk = (const float*)d_in[4];
    const float* Wv = (const float*)d_in[5];
    const float* bv = (const float*)d_in[6];
    const float* Wo = (const float*)d_in[7];
    const float* bo = (const float*)d_in[8];
    float* out = (float*)d_out;

    cudaFuncSetAttribute(attn_kernel,
                         cudaFuncAttributeMaxDynamicSharedMemorySize, SMEM_ATTN);

    qkv_kernel<<<dim3(Bdim*Tdim, 3, 1), 256>>>(X, Wq, bq, Wk, bk, Wv, bv);
    attn_kernel<<<Bdim*Tdim, 256, SMEM_ATTN>>>(Wo, bo, out);
}